// round 13
// baseline (speedup 1.0000x reference)
#include <cuda_runtime.h>
#include <cuda_bf16.h>
#include <cstdint>

static const int MAXN = 50000;

__device__ float g_Q [MAXN * 128];
__device__ float g_K [MAXN * 128];
__device__ float g_V [MAXN * 128];
__device__ float g_wV[MAXN * 128];
__device__ float g_z [MAXN * 8];

// ================= helpers =================
__device__ __forceinline__ uint32_t smem_u32(const void* p) {
    uint32_t a;
    asm("{ .reg .u64 t; cvta.to.shared.u64 t, %1; cvt.u32.u64 %0, t; }" : "=r"(a) : "l"(p));
    return a;
}
__device__ __forceinline__ void ldsm4(uint32_t& r0, uint32_t& r1, uint32_t& r2, uint32_t& r3,
                                      uint32_t addr) {
    asm volatile("ldmatrix.sync.aligned.m8n8.x4.shared.b16 {%0,%1,%2,%3}, [%4];"
                 : "=r"(r0), "=r"(r1), "=r"(r2), "=r"(r3) : "r"(addr));
}
__device__ __forceinline__ void mma16816(float* c,
                                         uint32_t a0, uint32_t a1, uint32_t a2, uint32_t a3,
                                         uint32_t b0, uint32_t b1) {
    asm volatile("mma.sync.aligned.m16n8k16.row.col.f32.bf16.bf16.f32 "
                 "{%0,%1,%2,%3}, {%4,%5,%6,%7}, {%8,%9}, {%0,%1,%2,%3};"
                 : "+f"(c[0]), "+f"(c[1]), "+f"(c[2]), "+f"(c[3])
                 : "r"(a0), "r"(a1), "r"(a2), "r"(a3), "r"(b0), "r"(b1));
}
__device__ __forceinline__ void red_v4(float* p, float a, float b, float c, float d) {
    asm volatile("red.global.add.v4.f32 [%0], {%1, %2, %3, %4};"
                 :: "l"(p), "f"(a), "f"(b), "f"(c), "f"(d) : "memory");
}
__device__ __forceinline__ void red_f32(float* p, float a) {
    asm volatile("red.global.add.f32 [%0], %1;" :: "l"(p), "f"(a) : "memory");
}
__device__ __forceinline__ void ldg_el8(const float* p, float v[8]) {
    uint32_t r0,r1,r2,r3,r4,r5,r6,r7;
    asm volatile("ld.global.nc.L2::evict_last.v8.b32 {%0,%1,%2,%3,%4,%5,%6,%7}, [%8];"
                 : "=r"(r0),"=r"(r1),"=r"(r2),"=r"(r3),"=r"(r4),"=r"(r5),"=r"(r6),"=r"(r7)
                 : "l"(p));
    v[0]=__uint_as_float(r0); v[1]=__uint_as_float(r1);
    v[2]=__uint_as_float(r2); v[3]=__uint_as_float(r3);
    v[4]=__uint_as_float(r4); v[5]=__uint_as_float(r5);
    v[6]=__uint_as_float(r6); v[7]=__uint_as_float(r7);
}
__device__ __forceinline__ void ldg_ef8(const float* p, float v[8]) {
    uint32_t r0,r1,r2,r3,r4,r5,r6,r7;
    asm volatile("ld.global.L2::evict_first.v8.b32 {%0,%1,%2,%3,%4,%5,%6,%7}, [%8];"
                 : "=r"(r0),"=r"(r1),"=r"(r2),"=r"(r3),"=r"(r4),"=r"(r5),"=r"(r6),"=r"(r7)
                 : "l"(p));
    v[0]=__uint_as_float(r0); v[1]=__uint_as_float(r1);
    v[2]=__uint_as_float(r2); v[3]=__uint_as_float(r3);
    v[4]=__uint_as_float(r4); v[5]=__uint_as_float(r5);
    v[6]=__uint_as_float(r6); v[7]=__uint_as_float(r7);
}
__device__ __forceinline__ void stg_ef8(float* p, const float v[8]) {
    asm volatile("st.global.L2::evict_first.v8.b32 [%0], {%1,%2,%3,%4,%5,%6,%7,%8};"
                 :: "l"(p),
                    "r"(__float_as_uint(v[0])), "r"(__float_as_uint(v[1])),
                    "r"(__float_as_uint(v[2])), "r"(__float_as_uint(v[3])),
                    "r"(__float_as_uint(v[4])), "r"(__float_as_uint(v[5])),
                    "r"(__float_as_uint(v[6])), "r"(__float_as_uint(v[7]))
                 : "memory");
}
// pack upper-16s of two fp32 words -> bf16x2 (truncation split, hi part)
__device__ __forceinline__ uint32_t prmt_hi(uint32_t a, uint32_t b) {
    uint32_t d; asm("prmt.b32 %0, %1, %2, 0x7632;" : "=r"(d) : "r"(a), "r"(b)); return d;
}
// pack two fp32 -> bf16x2 with round-to-nearest (lo residuals)
__device__ __forceinline__ uint32_t cvt_bf16x2(float l0, float l1) {
    uint32_t d; asm("cvt.rn.bf16x2.f32 %0, %1, %2;" : "=r"(d) : "f"(l1), "f"(l0)); return d;
}

// ---- smem layout: M128 tile, DOUBLE-BUFFERED A; padded 272B rows ----
#define SK    272
#define S_A0  0        // buf0: hi @0, lo @34816
#define S_A1  69632    // buf1: hi @69632, lo @104448
#define S_WH  139264
#define S_WL  174080
#define S_TOT 208896   // 204 KB <= 227 KB, 1 CTA/SM

#define GT 512   // 16 warps; warp grid 4M x 4N, warp tile M32 x N32

__device__ __forceinline__ void split_bf16(float x, __nv_bfloat16& h, __nv_bfloat16& l) {
    h = __float2bfloat16(x);
    l = __float2bfloat16(x - __bfloat162float(h));
}

__device__ __forceinline__ void conv_W(const float* __restrict__ W, char* smem, int tid) {
    for (int i = tid; i < 4096; i += GT) {
        int k = i >> 5, n4 = (i & 31) << 2;
        float4 w = *reinterpret_cast<const float4*>(W + k * 128 + n4);
        const float* wp = &w.x;
        #pragma unroll
        for (int j = 0; j < 4; j++) {
            __nv_bfloat16 h, l;
            split_bf16(wp[j], h, l);
            int off = (n4 + j) * SK + k * 2;
            *reinterpret_cast<__nv_bfloat16*>(smem + S_WH + off) = h;
            *reinterpret_cast<__nv_bfloat16*>(smem + S_WL + off) = l;
        }
    }
}

// A tile: 128 rows x 128 cols fp32 = 4096 float4, 512 threads -> 8 each
__device__ __forceinline__ void stage_A(const float* __restrict__ A, long rows, long t,
                                        float4* rg, int tid) {
    #pragma unroll
    for (int i = 0; i < 8; i++) {
        int idx = i * GT + tid;
        int m = idx >> 5, c4 = (idx & 31) << 2;
        long row = t * 128 + m;
        rg[i] = (row < rows) ? *reinterpret_cast<const float4*>(A + row * 128 + c4)
                             : make_float4(0.f, 0.f, 0.f, 0.f);
    }
}

// truncation split: hi = upper16 (PRMT pack), lo = exact residual rounded (CVT pack)
__device__ __forceinline__ void store_A(const float4* rg, char* smem, int bufoff, int tid) {
    #pragma unroll
    for (int i = 0; i < 8; i++) {
        int idx = i * GT + tid;
        int m = idx >> 5, c4 = (idx & 31) << 2;
        const float* ap = &rg[i].x;
        uint32_t b0 = __float_as_uint(ap[0]), b1 = __float_as_uint(ap[1]);
        uint32_t b2 = __float_as_uint(ap[2]), b3 = __float_as_uint(ap[3]);
        uint32_t hA = prmt_hi(b0, b1), hB = prmt_hi(b2, b3);
        float l0 = ap[0] - __uint_as_float(b0 & 0xFFFF0000u);
        float l1 = ap[1] - __uint_as_float(b1 & 0xFFFF0000u);
        float l2 = ap[2] - __uint_as_float(b2 & 0xFFFF0000u);
        float l3 = ap[3] - __uint_as_float(b3 & 0xFFFF0000u);
        uint32_t lA = cvt_bf16x2(l0, l1), lB = cvt_bf16x2(l2, l3);
        int off = m * SK + c4 * 2;
        *reinterpret_cast<uint2*>(smem + bufoff + off)         = make_uint2(hA, hB);
        *reinterpret_cast<uint2*>(smem + bufoff + 34816 + off) = make_uint2(lA, lB);
    }
}

// ================ GEMM: C[rows x 128] = A @ W + bias (tile M128 x N128) ================
__global__ void __launch_bounds__(GT, 1)
hmma_gemm_kernel(const float* __restrict__ A, const float* __restrict__ W,
                 const float* __restrict__ bias, float* __restrict__ C,
                 long rows, long ntiles) {
    extern __shared__ __align__(16) char smem[];
    const uint32_t sb = smem_u32(smem);
    const int tid = threadIdx.x, wid = tid >> 5, lane = tid & 31;
    const int mw = wid & 3, nw = wid >> 2;

    conv_W(W, smem, tid);

    const int q = lane >> 3, r = lane & 7;
    // A fragment offsets (relative to buffer base)
    const uint32_t aOff = (uint32_t)((mw * 32 + r + (q & 1) * 8) * SK + (q >> 1) * 16);
    // B fragment bases (absolute)
    const uint32_t bRow = (uint32_t)(nw * 32 + r + (q >> 1) * 8);
    const uint32_t b_kb = (uint32_t)((q & 1) * 16);
    const uint32_t bHb = sb + S_WH + bRow * SK + b_kb;
    const uint32_t bLb = sb + S_WL + bRow * SK + b_kb;

    float4 rg[8];
    long t = blockIdx.x;
    stage_A(A, rows, t, rg, tid);
    store_A(rg, smem, S_A0, tid);
    long tn = t + gridDim.x;
    bool have_next = (tn < ntiles);
    if (have_next) stage_A(A, rows, tn, rg, tid);
    __syncthreads();   // W + buf0 ready

    int cur = 0;
    while (true) {
        const uint32_t bufoff = cur ? S_A1 : S_A0;
        const uint32_t aH0 = sb + bufoff + aOff;
        const uint32_t aH1 = aH0 + 16 * SK;
        const uint32_t aL0 = aH0 + 34816;
        const uint32_t aL1 = aL0 + 16 * SK;

        // ---- mma over current buffer (issues first; tensor pipe fills) ----
        float acc[32];
        #pragma unroll
        for (int i = 0; i < 32; i++) acc[i] = 0.f;

        #pragma unroll
        for (int ks = 0; ks < 8; ks++) {
            const uint32_t ko = ks * 32;
            uint32_t h00, h01, h02, h03, h10, h11, h12, h13;
            uint32_t l00, l01, l02, l03, l10, l11, l12, l13;
            ldsm4(h00, h01, h02, h03, aH0 + ko);
            ldsm4(h10, h11, h12, h13, aH1 + ko);
            ldsm4(l00, l01, l02, l03, aL0 + ko);
            ldsm4(l10, l11, l12, l13, aL1 + ko);
            #pragma unroll
            for (int nb = 0; nb < 2; nb++) {
                const uint32_t off = (uint32_t)nb * (16 * SK) + ko;
                uint32_t xh0, xh1, xh2, xh3, xl0, xl1, xl2, xl3;
                ldsm4(xh0, xh1, xh2, xh3, bHb + off);
                ldsm4(xl0, xl1, xl2, xl3, bLb + off);
                float* c00 = acc + nb * 16;
                float* c01 = acc + nb * 16 + 4;
                float* c10 = acc + nb * 16 + 8;
                float* c11 = acc + nb * 16 + 12;
                mma16816(c00, h00, h01, h02, h03, xh0, xh1);
                mma16816(c01, h00, h01, h02, h03, xh2, xh3);
                mma16816(c10, h10, h11, h12, h13, xh0, xh1);
                mma16816(c11, h10, h11, h12, h13, xh2, xh3);
                mma16816(c00, h00, h01, h02, h03, xl0, xl1);
                mma16816(c01, h00, h01, h02, h03, xl2, xl3);
                mma16816(c10, h10, h11, h12, h13, xl0, xl1);
                mma16816(c11, h10, h11, h12, h13, xl2, xl3);
                mma16816(c00, l00, l01, l02, l03, xh0, xh1);
                mma16816(c01, l00, l01, l02, l03, xh2, xh3);
                mma16816(c10, l10, l11, l12, l13, xh0, xh1);
                mma16816(c11, l10, l11, l12, l13, xh2, xh3);
            }
        }

        // ---- convert next tile into the OTHER buffer (overlaps other warps' mma) ----
        if (have_next) {
            store_A(rg, smem, cur ? S_A0 : S_A1, tid);
            long tnn = tn + gridDim.x;
            if (tnn < ntiles) stage_A(A, rows, tnn, rg, tid);
        }

        // ---- epilogue: add bias, store C ----
        const long mbase = t * 128 + mw * 32;
        #pragma unroll
        for (int nb = 0; nb < 2; nb++) {
            #pragma unroll
            for (int n8 = 0; n8 < 2; n8++) {
                int col = nw * 32 + nb * 16 + n8 * 8 + (lane & 3) * 2;
                float2 bb = *reinterpret_cast<const float2*>(bias + col);
                #pragma unroll
                for (int mb = 0; mb < 2; mb++) {
                    const float* cp = acc + nb * 16 + mb * 8 + n8 * 4;
                    long r0 = mbase + mb * 16 + (lane >> 2);
                    long r1 = r0 + 8;
                    if (r0 < rows)
                        *reinterpret_cast<float2*>(C + r0 * 128 + col) =
                            make_float2(cp[0] + bb.x, cp[1] + bb.y);
                    if (r1 < rows)
                        *reinterpret_cast<float2*>(C + r1 * 128 + col) =
                            make_float2(cp[2] + bb.x, cp[3] + bb.y);
                }
            }
        }

        if (!have_next) break;
        __syncthreads();   // all mma(t) reads done before next store into this buffer
        t = tn;
        tn = t + gridDim.x;
        have_next = (tn < ntiles);
        cur ^= 1;
    }
}

// ================= non-GEMM kernels =================
__global__ void zero_kernel(int N) {
    int i = blockIdx.x * blockDim.x + threadIdx.x;
    if (i < N * 128) g_wV[i] = 0.f;
    if (i < N * 8)   g_z[i]  = 0.f;
}

// 2 edges per warp: lanes 0-15 -> edge 0, lanes 16-31 -> edge 1; 8 floats per lane.
__global__ void __launch_bounds__(256)
edge_epilogue_kernel(const float* __restrict__ envelope,
                     const int* __restrict__ src, const int* __restrict__ dst,
                     float* __restrict__ eout, long E) {
    long gw = (long)blockIdx.x * 8 + (threadIdx.x >> 5);
    int lane = threadIdx.x & 31;
    long ed = gw * 2 + (lane >> 4);
    if (ed >= E) return;

    int si = __ldg(src + ed);
    int di = __ldg(dst + ed);
    float env = __ldg(envelope + ed);

    int c = (lane & 15) * 8;
    float kv[8], qv[8], vv[8], pv[8];
    ldg_el8(g_K + (long)si * 128 + c, kv);
    ldg_el8(g_Q + (long)di * 128 + c, qv);
    ldg_el8(g_V + (long)si * 128 + c, vv);
    float* ep = eout + ed * 128 + c;
    ldg_ef8(ep, pv);

    float sc[8];
    float part = 0.f;
    #pragma unroll
    for (int i = 0; i < 8; i++) {
        sc[i] = kv[i] * qv[i] * 0.25f * pv[i];
        part += sc[i];
    }
    part += __shfl_xor_sync(0xFFFFFFFFu, part, 1);
    float s = __expf(fminf(fmaxf(part, -5.f), 5.f));
    float es = env * s;

    stg_ef8(ep, sc);

    float* w = g_wV + (long)di * 128 + c;
    red_v4(w,     vv[0] * es, vv[1] * es, vv[2] * es, vv[3] * es);
    red_v4(w + 4, vv[4] * es, vv[5] * es, vv[6] * es, vv[7] * es);
    if ((lane & 1) == 0) red_f32(g_z + (long)di * 8 + ((lane & 15) >> 1), s);
}

__global__ void norm_kernel(float* __restrict__ vout, int N) {
    int i = blockIdx.x * blockDim.x + threadIdx.x;
    if (i < N * 128) {
        int n = i >> 7;
        int c = i & 127;
        vout[i] = g_wV[i] / (g_z[n * 8 + (c >> 4)] + 1e-6f);
    }
}

extern "C" void kernel_launch(void* const* d_in, const int* in_sizes, int n_in,
                              void* d_out, int out_size) {
    const float* v        = (const float*)d_in[0];
    const float* e        = (const float*)d_in[1];
    const float* envelope = (const float*)d_in[2];
    const float* Wq       = (const float*)d_in[3];
    const float* bq       = (const float*)d_in[4];
    const float* Wk       = (const float*)d_in[5];
    const float* bk       = (const float*)d_in[6];
    const float* Wv       = (const float*)d_in[7];
    const float* bv       = (const float*)d_in[8];
    const float* We       = (const float*)d_in[9];
    const float* be       = (const float*)d_in[10];
    const int*   src      = (const int*)d_in[11];
    const int*   dst      = (const int*)d_in[12];

    int N = in_sizes[0] / 128;
    long E = in_sizes[11];

    float* out  = (float*)d_out;
    float* vout = out;
    float* eout = out + (long)N * 128;

    float *gq, *gk, *gv;
    cudaGetSymbolAddress((void**)&gq, g_Q);
    cudaGetSymbolAddress((void**)&gk, g_K);
    cudaGetSymbolAddress((void**)&gv, g_V);
    cudaFuncSetAttribute(hmma_gemm_kernel, cudaFuncAttributeMaxDynamicSharedMemorySize, S_TOT);

    long tilesN = (N + 127) / 128;
    long tilesE = (E + 127) / 128;
    int gridN = (int)((tilesN < 148) ? tilesN : 148);
    int gridE = (int)((tilesE < 148) ? tilesE : 148);

    zero_kernel<<<(N * 128 + 255) / 256, 256>>>(N);
    hmma_gemm_kernel<<<gridN, GT, S_TOT>>>(v, Wq, bq, gq, N, tilesN);
    hmma_gemm_kernel<<<gridN, GT, S_TOT>>>(v, Wk, bk, gk, N, tilesN);
    hmma_gemm_kernel<<<gridN, GT, S_TOT>>>(v, Wv, bv, gv, N, tilesN);
    hmma_gemm_kernel<<<gridE, GT, S_TOT>>>(e, We, be, eout, E, tilesE);
    edge_epilogue_kernel<<<(int)((E + 15) / 16), 256>>>(envelope, src, dst, eout, E);
    norm_kernel<<<(N * 128 + 255) / 256, 256>>>(vout, N);
}

// round 14
// speedup vs baseline: 1.0424x; 1.0424x over previous
#include <cuda_runtime.h>
#include <cuda_bf16.h>
#include <cstdint>

static const int MAXN = 50000;

__device__ float g_Q [MAXN * 128];
__device__ float g_K [MAXN * 128];
__device__ float g_V [MAXN * 128];
__device__ float g_wV[MAXN * 128];
__device__ float g_z [MAXN * 8];

// ================= helpers =================
__device__ __forceinline__ uint32_t smem_u32(const void* p) {
    uint32_t a;
    asm("{ .reg .u64 t; cvta.to.shared.u64 t, %1; cvt.u32.u64 %0, t; }" : "=r"(a) : "l"(p));
    return a;
}
__device__ __forceinline__ void ldsm4(uint32_t& r0, uint32_t& r1, uint32_t& r2, uint32_t& r3,
                                      uint32_t addr) {
    asm volatile("ldmatrix.sync.aligned.m8n8.x4.shared.b16 {%0,%1,%2,%3}, [%4];"
                 : "=r"(r0), "=r"(r1), "=r"(r2), "=r"(r3) : "r"(addr));
}
__device__ __forceinline__ void mma16816(float* c,
                                         uint32_t a0, uint32_t a1, uint32_t a2, uint32_t a3,
                                         uint32_t b0, uint32_t b1) {
    asm volatile("mma.sync.aligned.m16n8k16.row.col.f32.bf16.bf16.f32 "
                 "{%0,%1,%2,%3}, {%4,%5,%6,%7}, {%8,%9}, {%0,%1,%2,%3};"
                 : "+f"(c[0]), "+f"(c[1]), "+f"(c[2]), "+f"(c[3])
                 : "r"(a0), "r"(a1), "r"(a2), "r"(a3), "r"(b0), "r"(b1));
}
__device__ __forceinline__ void red_v4(float* p, float a, float b, float c, float d) {
    asm volatile("red.global.add.v4.f32 [%0], {%1, %2, %3, %4};"
                 :: "l"(p), "f"(a), "f"(b), "f"(c), "f"(d) : "memory");
}
__device__ __forceinline__ void red_f32(float* p, float a) {
    asm volatile("red.global.add.f32 [%0], %1;" :: "l"(p), "f"(a) : "memory");
}
__device__ __forceinline__ void ldg_el8(const float* p, float v[8]) {
    uint32_t r0,r1,r2,r3,r4,r5,r6,r7;
    asm volatile("ld.global.nc.L2::evict_last.v8.b32 {%0,%1,%2,%3,%4,%5,%6,%7}, [%8];"
                 : "=r"(r0),"=r"(r1),"=r"(r2),"=r"(r3),"=r"(r4),"=r"(r5),"=r"(r6),"=r"(r7)
                 : "l"(p));
    v[0]=__uint_as_float(r0); v[1]=__uint_as_float(r1);
    v[2]=__uint_as_float(r2); v[3]=__uint_as_float(r3);
    v[4]=__uint_as_float(r4); v[5]=__uint_as_float(r5);
    v[6]=__uint_as_float(r6); v[7]=__uint_as_float(r7);
}
__device__ __forceinline__ void ldg_ef8(const float* p, float v[8]) {
    uint32_t r0,r1,r2,r3,r4,r5,r6,r7;
    asm volatile("ld.global.L2::evict_first.v8.b32 {%0,%1,%2,%3,%4,%5,%6,%7}, [%8];"
                 : "=r"(r0),"=r"(r1),"=r"(r2),"=r"(r3),"=r"(r4),"=r"(r5),"=r"(r6),"=r"(r7)
                 : "l"(p));
    v[0]=__uint_as_float(r0); v[1]=__uint_as_float(r1);
    v[2]=__uint_as_float(r2); v[3]=__uint_as_float(r3);
    v[4]=__uint_as_float(r4); v[5]=__uint_as_float(r5);
    v[6]=__uint_as_float(r6); v[7]=__uint_as_float(r7);
}
__device__ __forceinline__ void stg_ef8(float* p, const float v[8]) {
    asm volatile("st.global.L2::evict_first.v8.b32 [%0], {%1,%2,%3,%4,%5,%6,%7,%8};"
                 :: "l"(p),
                    "r"(__float_as_uint(v[0])), "r"(__float_as_uint(v[1])),
                    "r"(__float_as_uint(v[2])), "r"(__float_as_uint(v[3])),
                    "r"(__float_as_uint(v[4])), "r"(__float_as_uint(v[5])),
                    "r"(__float_as_uint(v[6])), "r"(__float_as_uint(v[7]))
                 : "memory");
}

// ---- smem layout: padded 272B rows (16B pad -> ldmatrix conflict-free) ----
#define SK    272
#define S_AH  0
#define S_AL  34816
#define S_WH  69632
#define S_WL  104448
#define S_TOT 139264

#define GT 512   // 16 warps/CTA; warp grid 4M x 4N, warp tile M32 x N32

__device__ __forceinline__ void split_bf16(float x, __nv_bfloat16& h, __nv_bfloat16& l) {
    h = __float2bfloat16(x);
    l = __float2bfloat16(x - __bfloat162float(h));
}

__device__ __forceinline__ void conv_W(const float* __restrict__ W, char* smem, int tid) {
    for (int i = tid; i < 4096; i += GT) {
        int k = i >> 5, n4 = (i & 31) << 2;
        float4 w = *reinterpret_cast<const float4*>(W + k * 128 + n4);
        const float* wp = &w.x;
        #pragma unroll
        for (int j = 0; j < 4; j++) {
            __nv_bfloat16 h, l;
            split_bf16(wp[j], h, l);
            int off = (n4 + j) * SK + k * 2;
            *reinterpret_cast<__nv_bfloat16*>(smem + S_WH + off) = h;
            *reinterpret_cast<__nv_bfloat16*>(smem + S_WL + off) = l;
        }
    }
}

__device__ __forceinline__ void stage_A(const float* __restrict__ A, long rows, long t,
                                        float4* rg, int tid) {
    #pragma unroll
    for (int i = 0; i < 8; i++) {
        int idx = i * GT + tid;
        int m = idx >> 5, c4 = (idx & 31) << 2;
        long row = t * 128 + m;
        rg[i] = (row < rows) ? *reinterpret_cast<const float4*>(A + row * 128 + c4)
                             : make_float4(0.f, 0.f, 0.f, 0.f);
    }
}

__device__ __forceinline__ void store_A(const float4* rg, char* smem, int tid) {
    #pragma unroll
    for (int i = 0; i < 8; i++) {
        int idx = i * GT + tid;
        int m = idx >> 5, c4 = (idx & 31) << 2;
        const float* ap = &rg[i].x;
        __nv_bfloat16 h0, l0, h1, l1, h2, l2, h3, l3;
        split_bf16(ap[0], h0, l0); split_bf16(ap[1], h1, l1);
        split_bf16(ap[2], h2, l2); split_bf16(ap[3], h3, l3);
        __nv_bfloat162 hp0 = __halves2bfloat162(h0, h1), hp1 = __halves2bfloat162(h2, h3);
        __nv_bfloat162 lp0 = __halves2bfloat162(l0, l1), lp1 = __halves2bfloat162(l2, l3);
        int off = m * SK + c4 * 2;
        *reinterpret_cast<uint2*>(smem + S_AH + off) =
            make_uint2(*reinterpret_cast<uint32_t*>(&hp0), *reinterpret_cast<uint32_t*>(&hp1));
        *reinterpret_cast<uint2*>(smem + S_AL + off) =
            make_uint2(*reinterpret_cast<uint32_t*>(&lp0), *reinterpret_cast<uint32_t*>(&lp1));
    }
}

// ================ GEMM: C[rows x 128] = A @ W + bias (R11 config) ================
__global__ void __launch_bounds__(GT, 1)
hmma_gemm_kernel(const float* __restrict__ A, const float* __restrict__ W,
                 const float* __restrict__ bias, float* __restrict__ C,
                 long rows, long ntiles) {
    extern __shared__ __align__(16) char smem[];
    const uint32_t sb = smem_u32(smem);
    const int tid = threadIdx.x, wid = tid >> 5, lane = tid & 31;
    const int mw = wid & 3, nw = wid >> 2;

    conv_W(W, smem, tid);

    const int q = lane >> 3, r = lane & 7;
    const uint32_t aRow = (uint32_t)(mw * 32 + r + (q & 1) * 8);
    const uint32_t a_kb = (uint32_t)((q >> 1) * 16);
    const uint32_t aH0 = sb + S_AH + aRow * SK + a_kb;
    const uint32_t aH1 = aH0 + 16 * SK;
    const uint32_t aL0 = sb + S_AL + aRow * SK + a_kb;
    const uint32_t aL1 = aL0 + 16 * SK;
    const uint32_t bRow = (uint32_t)(nw * 32 + r + (q >> 1) * 8);
    const uint32_t b_kb = (uint32_t)((q & 1) * 16);
    const uint32_t bHb = sb + S_WH + bRow * SK + b_kb;
    const uint32_t bLb = sb + S_WL + bRow * SK + b_kb;

    float4 rg[8];
    long t = blockIdx.x;
    stage_A(A, rows, t, rg, tid);
    __syncthreads();

    for (; t < ntiles; ) {
        store_A(rg, smem, tid);
        __syncthreads();

        long tn = t + gridDim.x;
        if (tn < ntiles) stage_A(A, rows, tn, rg, tid);

        float acc[32];
        #pragma unroll
        for (int i = 0; i < 32; i++) acc[i] = 0.f;

        #pragma unroll
        for (int ks = 0; ks < 8; ks++) {
            const uint32_t ko = ks * 32;
            uint32_t h00, h01, h02, h03, h10, h11, h12, h13;
            uint32_t l00, l01, l02, l03, l10, l11, l12, l13;
            ldsm4(h00, h01, h02, h03, aH0 + ko);
            ldsm4(h10, h11, h12, h13, aH1 + ko);
            ldsm4(l00, l01, l02, l03, aL0 + ko);
            ldsm4(l10, l11, l12, l13, aL1 + ko);
            #pragma unroll
            for (int nb = 0; nb < 2; nb++) {
                const uint32_t off = (uint32_t)nb * (16 * SK) + ko;
                uint32_t xh0, xh1, xh2, xh3, xl0, xl1, xl2, xl3;
                ldsm4(xh0, xh1, xh2, xh3, bHb + off);
                ldsm4(xl0, xl1, xl2, xl3, bLb + off);
                float* c00 = acc + nb * 16;
                float* c01 = acc + nb * 16 + 4;
                float* c10 = acc + nb * 16 + 8;
                float* c11 = acc + nb * 16 + 12;
                mma16816(c00, h00, h01, h02, h03, xh0, xh1);
                mma16816(c01, h00, h01, h02, h03, xh2, xh3);
                mma16816(c10, h10, h11, h12, h13, xh0, xh1);
                mma16816(c11, h10, h11, h12, h13, xh2, xh3);
                mma16816(c00, h00, h01, h02, h03, xl0, xl1);
                mma16816(c01, h00, h01, h02, h03, xl2, xl3);
                mma16816(c10, h10, h11, h12, h13, xl0, xl1);
                mma16816(c11, h10, h11, h12, h13, xl2, xl3);
                mma16816(c00, l00, l01, l02, l03, xh0, xh1);
                mma16816(c01, l00, l01, l02, l03, xh2, xh3);
                mma16816(c10, l10, l11, l12, l13, xh0, xh1);
                mma16816(c11, l10, l11, l12, l13, xh2, xh3);
            }
        }

        const long mbase = t * 128 + mw * 32;
        #pragma unroll
        for (int nb = 0; nb < 2; nb++) {
            #pragma unroll
            for (int n8 = 0; n8 < 2; n8++) {
                int col = nw * 32 + nb * 16 + n8 * 8 + (lane & 3) * 2;
                float2 bb = *reinterpret_cast<const float2*>(bias + col);
                #pragma unroll
                for (int mb = 0; mb < 2; mb++) {
                    const float* cp = acc + nb * 16 + mb * 8 + n8 * 4;
                    long r0 = mbase + mb * 16 + (lane >> 2);
                    long r1 = r0 + 8;
                    if (r0 < rows)
                        *reinterpret_cast<float2*>(C + r0 * 128 + col) =
                            make_float2(cp[0] + bb.x, cp[1] + bb.y);
                    if (r1 < rows)
                        *reinterpret_cast<float2*>(C + r1 * 128 + col) =
                            make_float2(cp[2] + bb.x, cp[3] + bb.y);
                }
            }
        }
        __syncthreads();
        t = tn;
    }
}

// ================= non-GEMM kernels =================
__global__ void zero_kernel(int N) {
    long i = (long)blockIdx.x * blockDim.x + threadIdx.x;
    if (i < (long)N * 32) reinterpret_cast<float4*>(g_wV)[i] = make_float4(0.f, 0.f, 0.f, 0.f);
    if (i < (long)N * 2)  reinterpret_cast<float4*>(g_z)[i]  = make_float4(0.f, 0.f, 0.f, 0.f);
}

// persistent epilogue over edge range [e0, e1): 2 edges/warp/iter, 8 floats/lane
__global__ void __launch_bounds__(256)
edge_epilogue_kernel(const float* __restrict__ envelope,
                     const int* __restrict__ src, const int* __restrict__ dst,
                     float* __restrict__ eout, long e0, long e1) {
    int lane = threadIdx.x & 31;
    long warpSlot = (long)blockIdx.x * 8 + (threadIdx.x >> 5);
    long stride = (long)gridDim.x * 16;   // 8 warps/CTA * 2 edges/warp

    for (long ed = e0 + warpSlot * 2 + (lane >> 4); ed < e1; ed += stride) {
        int si = __ldg(src + ed);
        int di = __ldg(dst + ed);
        float env = __ldg(envelope + ed);

        int c = (lane & 15) * 8;
        float kv[8], qv[8], vv[8], pv[8];
        ldg_el8(g_K + (long)si * 128 + c, kv);
        ldg_el8(g_Q + (long)di * 128 + c, qv);
        ldg_el8(g_V + (long)si * 128 + c, vv);
        float* ep = eout + ed * 128 + c;
        ldg_ef8(ep, pv);

        float sc[8];
        float part = 0.f;
        #pragma unroll
        for (int i = 0; i < 8; i++) {
            sc[i] = kv[i] * qv[i] * 0.25f * pv[i];
            part += sc[i];
        }
        part += __shfl_xor_sync(0xFFFFFFFFu, part, 1);
        float s = __expf(fminf(fmaxf(part, -5.f), 5.f));
        float es = env * s;

        stg_ef8(ep, sc);

        float* w = g_wV + (long)di * 128 + c;
        red_v4(w,     vv[0] * es, vv[1] * es, vv[2] * es, vv[3] * es);
        red_v4(w + 4, vv[4] * es, vv[5] * es, vv[6] * es, vv[7] * es);
        if ((lane & 1) == 0) red_f32(g_z + (long)di * 8 + ((lane & 15) >> 1), s);
    }
}

__global__ void norm_kernel(float* __restrict__ vout, int N) {
    long i = (long)blockIdx.x * blockDim.x + threadIdx.x;
    if (i < (long)N * 32) {
        int n  = (int)(i >> 5);
        int c4 = (int)(i & 31);
        float4 w = reinterpret_cast<const float4*>(g_wV)[i];
        float zz = g_z[n * 8 + (c4 >> 2)] + 1e-6f;
        float inv = 1.0f / zz;
        reinterpret_cast<float4*>(vout)[i] =
            make_float4(w.x * inv, w.y * inv, w.z * inv, w.w * inv);
    }
}

extern "C" void kernel_launch(void* const* d_in, const int* in_sizes, int n_in,
                              void* d_out, int out_size) {
    const float* v        = (const float*)d_in[0];
    const float* e        = (const float*)d_in[1];
    const float* envelope = (const float*)d_in[2];
    const float* Wq       = (const float*)d_in[3];
    const float* bq       = (const float*)d_in[4];
    const float* Wk       = (const float*)d_in[5];
    const float* bk       = (const float*)d_in[6];
    const float* Wv       = (const float*)d_in[7];
    const float* bv       = (const float*)d_in[8];
    const float* We       = (const float*)d_in[9];
    const float* be       = (const float*)d_in[10];
    const int*   src      = (const int*)d_in[11];
    const int*   dst      = (const int*)d_in[12];

    int N = in_sizes[0] / 128;
    long E = in_sizes[11];

    float* out  = (float*)d_out;
    float* vout = out;
    float* eout = out + (long)N * 128;

    float *gq, *gk, *gv;
    cudaGetSymbolAddress((void**)&gq, g_Q);
    cudaGetSymbolAddress((void**)&gk, g_K);
    cudaGetSymbolAddress((void**)&gv, g_V);
    cudaFuncSetAttribute(hmma_gemm_kernel, cudaFuncAttributeMaxDynamicSharedMemorySize, S_TOT);

    long tilesN = (N + 127) / 128;
    int gridN = (int)((tilesN < 148) ? tilesN : 148);

    // side stream + events for GEMM/epilogue overlap (created fresh each call; capture-safe)
    cudaStream_t s1;
    cudaStreamCreateWithFlags(&s1, cudaStreamNonBlocking);
    cudaEvent_t evG[4], evE;
    for (int i = 0; i < 4; i++) cudaEventCreateWithFlags(&evG[i], cudaEventDisableTiming);
    cudaEventCreateWithFlags(&evE, cudaEventDisableTiming);

    zero_kernel<<<(int)(((long)N * 32 + 255) / 256), 256>>>(N);
    hmma_gemm_kernel<<<gridN, GT, S_TOT>>>(v, Wq, bq, gq, N, tilesN);
    hmma_gemm_kernel<<<gridN, GT, S_TOT>>>(v, Wk, bk, gk, N, tilesN);
    hmma_gemm_kernel<<<gridN, GT, S_TOT>>>(v, Wv, bv, gv, N, tilesN);

    // edge GEMM in 4 tile-aligned chunks on stream 0 (grid 120 -> 28 SMs left for sidecar)
    const long totTiles = (E + 127) / 128;
    const long chunkTiles = (totTiles + 3) / 4;
    long eStart[5];
    eStart[0] = 0;
    for (int c = 0; c < 4; c++) {
        long t0 = c * chunkTiles;
        long t1 = (c + 1) * chunkTiles; if (t1 > totTiles) t1 = totTiles;
        if (t0 >= t1) { eStart[c + 1] = eStart[c]; cudaEventRecord(evG[c], 0); continue; }
        long rowStart = t0 * 128;
        long rows = E - rowStart; long chunkRows = (t1 - t0) * 128;
        if (rows > chunkRows) rows = chunkRows;
        long ct = t1 - t0;
        int g = (int)((ct < 120) ? ct : 120);
        hmma_gemm_kernel<<<g, GT, S_TOT>>>(e + rowStart * 128, We, be,
                                           eout + rowStart * 128, rows, ct);
        cudaEventRecord(evG[c], 0);
        eStart[c + 1] = rowStart + rows;
    }

    // sidecar epilogue on s1: chunks 0-2 persistent (sized for ~28 free SMs), chunk 3 full width
    for (int c = 0; c < 4; c++) {
        cudaStreamWaitEvent(s1, evG[c], 0);
        long e0 = eStart[c], e1 = eStart[c + 1];
        if (e0 >= e1) continue;
        if (c < 3) {
            edge_epilogue_kernel<<<160, 256, 0, s1>>>(envelope, src, dst, eout, e0, e1);
        } else {
            long nw = (e1 - e0 + 1) / 2;
            int g = (int)((nw + 7) / 8);
            edge_epilogue_kernel<<<g, 256, 0, s1>>>(envelope, src, dst, eout, e0, e1);
        }
    }
    cudaEventRecord(evE, s1);
    cudaStreamWaitEvent(0, evE, 0);

    norm_kernel<<<(int)(((long)N * 32 + 255) / 256), 256>>>(vout, N);
}

// round 15
// speedup vs baseline: 1.2090x; 1.1597x over previous
#include <cuda_runtime.h>
#include <cuda_bf16.h>
#include <cstdint>

static const int MAXN = 50000;

__device__ float g_Q [MAXN * 128];
__device__ float g_K [MAXN * 128];
__device__ float g_V [MAXN * 128];
__device__ float g_wV[MAXN * 128];
__device__ float g_z [MAXN * 8];

// ================= helpers =================
__device__ __forceinline__ uint32_t smem_u32(const void* p) {
    uint32_t a;
    asm("{ .reg .u64 t; cvta.to.shared.u64 t, %1; cvt.u32.u64 %0, t; }" : "=r"(a) : "l"(p));
    return a;
}
__device__ __forceinline__ void ldsm4(uint32_t& r0, uint32_t& r1, uint32_t& r2, uint32_t& r3,
                                      uint32_t addr) {
    asm volatile("ldmatrix.sync.aligned.m8n8.x4.shared.b16 {%0,%1,%2,%3}, [%4];"
                 : "=r"(r0), "=r"(r1), "=r"(r2), "=r"(r3) : "r"(addr));
}
__device__ __forceinline__ void mma16816(float* c,
                                         uint32_t a0, uint32_t a1, uint32_t a2, uint32_t a3,
                                         uint32_t b0, uint32_t b1) {
    asm volatile("mma.sync.aligned.m16n8k16.row.col.f32.bf16.bf16.f32 "
                 "{%0,%1,%2,%3}, {%4,%5,%6,%7}, {%8,%9}, {%0,%1,%2,%3};"
                 : "+f"(c[0]), "+f"(c[1]), "+f"(c[2]), "+f"(c[3])
                 : "r"(a0), "r"(a1), "r"(a2), "r"(a3), "r"(b0), "r"(b1));
}
__device__ __forceinline__ void red_v4(float* p, float a, float b, float c, float d) {
    asm volatile("red.global.add.v4.f32 [%0], {%1, %2, %3, %4};"
                 :: "l"(p), "f"(a), "f"(b), "f"(c), "f"(d) : "memory");
}
__device__ __forceinline__ void red_f32(float* p, float a) {
    asm volatile("red.global.add.f32 [%0], %1;" :: "l"(p), "f"(a) : "memory");
}
__device__ __forceinline__ void ldg_el8(const float* p, float v[8]) {
    uint32_t r0,r1,r2,r3,r4,r5,r6,r7;
    asm volatile("ld.global.nc.L2::evict_last.v8.b32 {%0,%1,%2,%3,%4,%5,%6,%7}, [%8];"
                 : "=r"(r0),"=r"(r1),"=r"(r2),"=r"(r3),"=r"(r4),"=r"(r5),"=r"(r6),"=r"(r7)
                 : "l"(p));
    v[0]=__uint_as_float(r0); v[1]=__uint_as_float(r1);
    v[2]=__uint_as_float(r2); v[3]=__uint_as_float(r3);
    v[4]=__uint_as_float(r4); v[5]=__uint_as_float(r5);
    v[6]=__uint_as_float(r6); v[7]=__uint_as_float(r7);
}
__device__ __forceinline__ void ldg_ef8(const float* p, float v[8]) {
    uint32_t r0,r1,r2,r3,r4,r5,r6,r7;
    asm volatile("ld.global.L2::evict_first.v8.b32 {%0,%1,%2,%3,%4,%5,%6,%7}, [%8];"
                 : "=r"(r0),"=r"(r1),"=r"(r2),"=r"(r3),"=r"(r4),"=r"(r5),"=r"(r6),"=r"(r7)
                 : "l"(p));
    v[0]=__uint_as_float(r0); v[1]=__uint_as_float(r1);
    v[2]=__uint_as_float(r2); v[3]=__uint_as_float(r3);
    v[4]=__uint_as_float(r4); v[5]=__uint_as_float(r5);
    v[6]=__uint_as_float(r6); v[7]=__uint_as_float(r7);
}
__device__ __forceinline__ void stg_ef8(float* p, const float v[8]) {
    asm volatile("st.global.L2::evict_first.v8.b32 [%0], {%1,%2,%3,%4,%5,%6,%7,%8};"
                 :: "l"(p),
                    "r"(__float_as_uint(v[0])), "r"(__float_as_uint(v[1])),
                    "r"(__float_as_uint(v[2])), "r"(__float_as_uint(v[3])),
                    "r"(__float_as_uint(v[4])), "r"(__float_as_uint(v[5])),
                    "r"(__float_as_uint(v[6])), "r"(__float_as_uint(v[7]))
                 : "memory");
}

// ---- smem layout: padded 272B rows (16B pad -> ldmatrix conflict-free) ----
#define SK    272
#define S_AH  0
#define S_AL  34816
#define S_WH  69632
#define S_WL  104448
#define S_TOT 139264

#define GT 512   // 16 warps/CTA; warp grid 4M x 4N, warp tile M32 x N32

__device__ __forceinline__ void split_bf16(float x, __nv_bfloat16& h, __nv_bfloat16& l) {
    h = __float2bfloat16(x);
    l = __float2bfloat16(x - __bfloat162float(h));
}

__device__ __forceinline__ void conv_W(const float* __restrict__ W, char* smem, int tid) {
    for (int i = tid; i < 4096; i += GT) {
        int k = i >> 5, n4 = (i & 31) << 2;
        float4 w = *reinterpret_cast<const float4*>(W + k * 128 + n4);
        const float* wp = &w.x;
        #pragma unroll
        for (int j = 0; j < 4; j++) {
            __nv_bfloat16 h, l;
            split_bf16(wp[j], h, l);
            int off = (n4 + j) * SK + k * 2;
            *reinterpret_cast<__nv_bfloat16*>(smem + S_WH + off) = h;
            *reinterpret_cast<__nv_bfloat16*>(smem + S_WL + off) = l;
        }
    }
}

__device__ __forceinline__ void stage_A(const float* __restrict__ A, long rows, long t,
                                        float4* rg, int tid) {
    #pragma unroll
    for (int i = 0; i < 8; i++) {
        int idx = i * GT + tid;
        int m = idx >> 5, c4 = (idx & 31) << 2;
        long row = t * 128 + m;
        rg[i] = (row < rows) ? *reinterpret_cast<const float4*>(A + row * 128 + c4)
                             : make_float4(0.f, 0.f, 0.f, 0.f);
    }
}

__device__ __forceinline__ void store_A(const float4* rg, char* smem, int tid) {
    #pragma unroll
    for (int i = 0; i < 8; i++) {
        int idx = i * GT + tid;
        int m = idx >> 5, c4 = (idx & 31) << 2;
        const float* ap = &rg[i].x;
        __nv_bfloat16 h0, l0, h1, l1, h2, l2, h3, l3;
        split_bf16(ap[0], h0, l0); split_bf16(ap[1], h1, l1);
        split_bf16(ap[2], h2, l2); split_bf16(ap[3], h3, l3);
        __nv_bfloat162 hp0 = __halves2bfloat162(h0, h1), hp1 = __halves2bfloat162(h2, h3);
        __nv_bfloat162 lp0 = __halves2bfloat162(l0, l1), lp1 = __halves2bfloat162(l2, l3);
        int off = m * SK + c4 * 2;
        *reinterpret_cast<uint2*>(smem + S_AH + off) =
            make_uint2(*reinterpret_cast<uint32_t*>(&hp0), *reinterpret_cast<uint32_t*>(&hp1));
        *reinterpret_cast<uint2*>(smem + S_AL + off) =
            make_uint2(*reinterpret_cast<uint32_t*>(&lp0), *reinterpret_cast<uint32_t*>(&lp1));
    }
}

// ================ GEMM: C[rows x 128] = A @ W + bias (R11 config) ================
__global__ void __launch_bounds__(GT, 1)
hmma_gemm_kernel(const float* __restrict__ A, const float* __restrict__ W,
                 const float* __restrict__ bias, float* __restrict__ C,
                 long rows, long ntiles) {
    extern __shared__ __align__(16) char smem[];
    const uint32_t sb = smem_u32(smem);
    const int tid = threadIdx.x, wid = tid >> 5, lane = tid & 31;
    const int mw = wid & 3, nw = wid >> 2;

    conv_W(W, smem, tid);

    const int q = lane >> 3, r = lane & 7;
    const uint32_t aRow = (uint32_t)(mw * 32 + r + (q & 1) * 8);
    const uint32_t a_kb = (uint32_t)((q >> 1) * 16);
    const uint32_t aH0 = sb + S_AH + aRow * SK + a_kb;
    const uint32_t aH1 = aH0 + 16 * SK;
    const uint32_t aL0 = sb + S_AL + aRow * SK + a_kb;
    const uint32_t aL1 = aL0 + 16 * SK;
    const uint32_t bRow = (uint32_t)(nw * 32 + r + (q >> 1) * 8);
    const uint32_t b_kb = (uint32_t)((q & 1) * 16);
    const uint32_t bHb = sb + S_WH + bRow * SK + b_kb;
    const uint32_t bLb = sb + S_WL + bRow * SK + b_kb;

    float4 rg[8];
    long t = blockIdx.x;
    stage_A(A, rows, t, rg, tid);
    __syncthreads();

    for (; t < ntiles; ) {
        store_A(rg, smem, tid);
        __syncthreads();

        long tn = t + gridDim.x;
        if (tn < ntiles) stage_A(A, rows, tn, rg, tid);

        float acc[32];
        #pragma unroll
        for (int i = 0; i < 32; i++) acc[i] = 0.f;

        #pragma unroll
        for (int ks = 0; ks < 8; ks++) {
            const uint32_t ko = ks * 32;
            uint32_t h00, h01, h02, h03, h10, h11, h12, h13;
            uint32_t l00, l01, l02, l03, l10, l11, l12, l13;
            ldsm4(h00, h01, h02, h03, aH0 + ko);
            ldsm4(h10, h11, h12, h13, aH1 + ko);
            ldsm4(l00, l01, l02, l03, aL0 + ko);
            ldsm4(l10, l11, l12, l13, aL1 + ko);
            #pragma unroll
            for (int nb = 0; nb < 2; nb++) {
                const uint32_t off = (uint32_t)nb * (16 * SK) + ko;
                uint32_t xh0, xh1, xh2, xh3, xl0, xl1, xl2, xl3;
                ldsm4(xh0, xh1, xh2, xh3, bHb + off);
                ldsm4(xl0, xl1, xl2, xl3, bLb + off);
                float* c00 = acc + nb * 16;
                float* c01 = acc + nb * 16 + 4;
                float* c10 = acc + nb * 16 + 8;
                float* c11 = acc + nb * 16 + 12;
                mma16816(c00, h00, h01, h02, h03, xh0, xh1);
                mma16816(c01, h00, h01, h02, h03, xh2, xh3);
                mma16816(c10, h10, h11, h12, h13, xh0, xh1);
                mma16816(c11, h10, h11, h12, h13, xh2, xh3);
                mma16816(c00, h00, h01, h02, h03, xl0, xl1);
                mma16816(c01, h00, h01, h02, h03, xl2, xl3);
                mma16816(c10, h10, h11, h12, h13, xl0, xl1);
                mma16816(c11, h10, h11, h12, h13, xl2, xl3);
                mma16816(c00, l00, l01, l02, l03, xh0, xh1);
                mma16816(c01, l00, l01, l02, l03, xh2, xh3);
                mma16816(c10, l10, l11, l12, l13, xh0, xh1);
                mma16816(c11, l10, l11, l12, l13, xh2, xh3);
            }
        }

        const long mbase = t * 128 + mw * 32;
        #pragma unroll
        for (int nb = 0; nb < 2; nb++) {
            #pragma unroll
            for (int n8 = 0; n8 < 2; n8++) {
                int col = nw * 32 + nb * 16 + n8 * 8 + (lane & 3) * 2;
                float2 bb = *reinterpret_cast<const float2*>(bias + col);
                #pragma unroll
                for (int mb = 0; mb < 2; mb++) {
                    const float* cp = acc + nb * 16 + mb * 8 + n8 * 4;
                    long r0 = mbase + mb * 16 + (lane >> 2);
                    long r1 = r0 + 8;
                    if (r0 < rows)
                        *reinterpret_cast<float2*>(C + r0 * 128 + col) =
                            make_float2(cp[0] + bb.x, cp[1] + bb.y);
                    if (r1 < rows)
                        *reinterpret_cast<float2*>(C + r1 * 128 + col) =
                            make_float2(cp[2] + bb.x, cp[3] + bb.y);
                }
            }
        }
        __syncthreads();
        t = tn;
    }
}

// ================= non-GEMM kernels =================
__global__ void zero_kernel(int N) {
    long i = (long)blockIdx.x * blockDim.x + threadIdx.x;
    if (i < (long)N * 32) reinterpret_cast<float4*>(g_wV)[i] = make_float4(0.f, 0.f, 0.f, 0.f);
    if (i < (long)N * 2)  reinterpret_cast<float4*>(g_z)[i]  = make_float4(0.f, 0.f, 0.f, 0.f);
}

// epilogue over edge range [e0, e1): 2 edges/warp, 8 floats/lane
__global__ void __launch_bounds__(256)
edge_epilogue_kernel(const float* __restrict__ envelope,
                     const int* __restrict__ src, const int* __restrict__ dst,
                     float* __restrict__ eout, long e0, long e1) {
    int lane = threadIdx.x & 31;
    long gw = (long)blockIdx.x * 8 + (threadIdx.x >> 5);
    long ed = e0 + gw * 2 + (lane >> 4);
    if (ed >= e1) return;

    int si = __ldg(src + ed);
    int di = __ldg(dst + ed);
    float env = __ldg(envelope + ed);

    int c = (lane & 15) * 8;
    float kv[8], qv[8], vv[8], pv[8];
    ldg_el8(g_K + (long)si * 128 + c, kv);
    ldg_el8(g_Q + (long)di * 128 + c, qv);
    ldg_el8(g_V + (long)si * 128 + c, vv);
    float* ep = eout + ed * 128 + c;
    ldg_ef8(ep, pv);

    float sc[8];
    float part = 0.f;
    #pragma unroll
    for (int i = 0; i < 8; i++) {
        sc[i] = kv[i] * qv[i] * 0.25f * pv[i];
        part += sc[i];
    }
    part += __shfl_xor_sync(0xFFFFFFFFu, part, 1);
    float s = __expf(fminf(fmaxf(part, -5.f), 5.f));
    float es = env * s;

    stg_ef8(ep, sc);

    float* w = g_wV + (long)di * 128 + c;
    red_v4(w,     vv[0] * es, vv[1] * es, vv[2] * es, vv[3] * es);
    red_v4(w + 4, vv[4] * es, vv[5] * es, vv[6] * es, vv[7] * es);
    if ((lane & 1) == 0) red_f32(g_z + (long)di * 8 + ((lane & 15) >> 1), s);
}

__global__ void norm_kernel(float* __restrict__ vout, int N) {
    long i = (long)blockIdx.x * blockDim.x + threadIdx.x;
    if (i < (long)N * 32) {
        int n  = (int)(i >> 5);
        int c4 = (int)(i & 31);
        float4 w = reinterpret_cast<const float4*>(g_wV)[i];
        float zz = g_z[n * 8 + (c4 >> 2)] + 1e-6f;
        float inv = 1.0f / zz;
        reinterpret_cast<float4*>(vout)[i] =
            make_float4(w.x * inv, w.y * inv, w.z * inv, w.w * inv);
    }
}

extern "C" void kernel_launch(void* const* d_in, const int* in_sizes, int n_in,
                              void* d_out, int out_size) {
    const float* v        = (const float*)d_in[0];
    const float* e        = (const float*)d_in[1];
    const float* envelope = (const float*)d_in[2];
    const float* Wq       = (const float*)d_in[3];
    const float* bq       = (const float*)d_in[4];
    const float* Wk       = (const float*)d_in[5];
    const float* bk       = (const float*)d_in[6];
    const float* Wv       = (const float*)d_in[7];
    const float* bv       = (const float*)d_in[8];
    const float* We       = (const float*)d_in[9];
    const float* be       = (const float*)d_in[10];
    const int*   src      = (const int*)d_in[11];
    const int*   dst      = (const int*)d_in[12];

    int N = in_sizes[0] / 128;
    long E = in_sizes[11];

    float* out  = (float*)d_out;
    float* vout = out;
    float* eout = out + (long)N * 128;

    float *gq, *gk, *gv;
    cudaGetSymbolAddress((void**)&gq, g_Q);
    cudaGetSymbolAddress((void**)&gk, g_K);
    cudaGetSymbolAddress((void**)&gv, g_V);
    cudaFuncSetAttribute(hmma_gemm_kernel, cudaFuncAttributeMaxDynamicSharedMemorySize, S_TOT);

    long tilesN = (N + 127) / 128;
    int gridN = (int)((tilesN < 148) ? tilesN : 148);

    zero_kernel<<<(int)(((long)N * 32 + 255) / 256), 256>>>(N);
    hmma_gemm_kernel<<<gridN, GT, S_TOT>>>(v, Wq, bq, gq, N, tilesN);
    hmma_gemm_kernel<<<gridN, GT, S_TOT>>>(v, Wk, bk, gk, N, tilesN);
    hmma_gemm_kernel<<<gridN, GT, S_TOT>>>(v, Wv, bv, gv, N, tilesN);

    // ---- edge GEMM + epilogue interleaved in chunks (proj stays L2-resident) ----
    const long totTiles = (E + 127) / 128;
    const int NCHUNK = 8;                         // ~51 MB proj per chunk (< L2)
    const long chunkTiles = (totTiles + NCHUNK - 1) / NCHUNK;
    for (int c = 0; c < NCHUNK; c++) {
        long t0 = (long)c * chunkTiles;
        long t1 = t0 + chunkTiles; if (t1 > totTiles) t1 = totTiles;
        if (t0 >= t1) break;
        long rowStart = t0 * 128;
        long rows = E - rowStart;
        long chunkRows = (t1 - t0) * 128;
        if (rows > chunkRows) rows = chunkRows;
        long ct = t1 - t0;
        int g = (int)((ct < 148) ? ct : 148);
        hmma_gemm_kernel<<<g, GT, S_TOT>>>(e + rowStart * 128, We, be,
                                           eout + rowStart * 128, rows, ct);
        long nw = (rows + 1) / 2;
        int ge = (int)((nw + 7) / 8);
        edge_epilogue_kernel<<<ge, 256>>>(envelope, src, dst, eout,
                                          rowStart, rowStart + rows);
    }

    norm_kernel<<<(int)(((long)N * 32 + 255) / 256), 256>>>(vout, N);
}

// round 16
// speedup vs baseline: 1.7373x; 1.4370x over previous
#include <cuda_runtime.h>
#include <cuda_fp16.h>
#include <cstdint>

static const int MAXN = 50000;

__device__ float g_Q [MAXN * 128];
__device__ float g_K [MAXN * 128];
__device__ float g_V [MAXN * 128];
__device__ float g_wV[MAXN * 128];
__device__ float g_z [MAXN * 8];

// ================= helpers =================
__device__ __forceinline__ uint32_t smem_u32(const void* p) {
    uint32_t a;
    asm("{ .reg .u64 t; cvta.to.shared.u64 t, %1; cvt.u32.u64 %0, t; }" : "=r"(a) : "l"(p));
    return a;
}
__device__ __forceinline__ void ldsm4(uint32_t& r0, uint32_t& r1, uint32_t& r2, uint32_t& r3,
                                      uint32_t addr) {
    asm volatile("ldmatrix.sync.aligned.m8n8.x4.shared.b16 {%0,%1,%2,%3}, [%4];"
                 : "=r"(r0), "=r"(r1), "=r"(r2), "=r"(r3) : "r"(addr));
}
__device__ __forceinline__ void mma16816(float* c,
                                         uint32_t a0, uint32_t a1, uint32_t a2, uint32_t a3,
                                         uint32_t b0, uint32_t b1) {
    asm volatile("mma.sync.aligned.m16n8k16.row.col.f32.f16.f16.f32 "
                 "{%0,%1,%2,%3}, {%4,%5,%6,%7}, {%8,%9}, {%0,%1,%2,%3};"
                 : "+f"(c[0]), "+f"(c[1]), "+f"(c[2]), "+f"(c[3])
                 : "r"(a0), "r"(a1), "r"(a2), "r"(a3), "r"(b0), "r"(b1));
}
__device__ __forceinline__ void red_v4(float* p, float a, float b, float c, float d) {
    asm volatile("red.global.add.v4.f32 [%0], {%1, %2, %3, %4};"
                 :: "l"(p), "f"(a), "f"(b), "f"(c), "f"(d) : "memory");
}
__device__ __forceinline__ void red_f32(float* p, float a) {
    asm volatile("red.global.add.f32 [%0], %1;" :: "l"(p), "f"(a) : "memory");
}
__device__ __forceinline__ void ldg_el8(const float* p, float v[8]) {
    uint32_t r0,r1,r2,r3,r4,r5,r6,r7;
    asm volatile("ld.global.nc.L2::evict_last.v8.b32 {%0,%1,%2,%3,%4,%5,%6,%7}, [%8];"
                 : "=r"(r0),"=r"(r1),"=r"(r2),"=r"(r3),"=r"(r4),"=r"(r5),"=r"(r6),"=r"(r7)
                 : "l"(p));
    v[0]=__uint_as_float(r0); v[1]=__uint_as_float(r1);
    v[2]=__uint_as_float(r2); v[3]=__uint_as_float(r3);
    v[4]=__uint_as_float(r4); v[5]=__uint_as_float(r5);
    v[6]=__uint_as_float(r6); v[7]=__uint_as_float(r7);
}
__device__ __forceinline__ void ldg_ef8(const float* p, float v[8]) {
    uint32_t r0,r1,r2,r3,r4,r5,r6,r7;
    asm volatile("ld.global.L2::evict_first.v8.b32 {%0,%1,%2,%3,%4,%5,%6,%7}, [%8];"
                 : "=r"(r0),"=r"(r1),"=r"(r2),"=r"(r3),"=r"(r4),"=r"(r5),"=r"(r6),"=r"(r7)
                 : "l"(p));
    v[0]=__uint_as_float(r0); v[1]=__uint_as_float(r1);
    v[2]=__uint_as_float(r2); v[3]=__uint_as_float(r3);
    v[4]=__uint_as_float(r4); v[5]=__uint_as_float(r5);
    v[6]=__uint_as_float(r6); v[7]=__uint_as_float(r7);
}
__device__ __forceinline__ void stg_ef8(float* p, const float v[8]) {
    asm volatile("st.global.L2::evict_first.v8.b32 [%0], {%1,%2,%3,%4,%5,%6,%7,%8};"
                 :: "l"(p),
                    "r"(__float_as_uint(v[0])), "r"(__float_as_uint(v[1])),
                    "r"(__float_as_uint(v[2])), "r"(__float_as_uint(v[3])),
                    "r"(__float_as_uint(v[4])), "r"(__float_as_uint(v[5])),
                    "r"(__float_as_uint(v[6])), "r"(__float_as_uint(v[7]))
                 : "memory");
}

// ---- smem layout: padded 272B rows (16B pad -> ldmatrix conflict-free) ----
// A: single fp16 (34816B). W: fp16 hi + fp16 lo (34816B each). Total 102KB.
#define SK    272
#define S_AS  0
#define S_WH  34816
#define S_WL  69632
#define S_TOT 104448

#define GT 512   // 16 warps/CTA; warp grid 4M x 4N, warp tile M32 x N32

__device__ __forceinline__ void conv_W(const float* __restrict__ W, char* smem, int tid) {
    for (int i = tid; i < 4096; i += GT) {
        int k = i >> 5, n4 = (i & 31) << 2;
        float4 w = *reinterpret_cast<const float4*>(W + k * 128 + n4);
        const float* wp = &w.x;
        #pragma unroll
        for (int j = 0; j < 4; j++) {
            __half h = __float2half_rn(wp[j]);
            __half l = __float2half_rn(wp[j] - __half2float(h));
            int off = (n4 + j) * SK + k * 2;
            *reinterpret_cast<__half*>(smem + S_WH + off) = h;
            *reinterpret_cast<__half*>(smem + S_WL + off) = l;
        }
    }
}

__device__ __forceinline__ void stage_A(const float* __restrict__ A, long rows, long t,
                                        float4* rg, int tid) {
    #pragma unroll
    for (int i = 0; i < 8; i++) {
        int idx = i * GT + tid;
        int m = idx >> 5, c4 = (idx & 31) << 2;
        long row = t * 128 + m;
        rg[i] = (row < rows) ? *reinterpret_cast<const float4*>(A + row * 128 + c4)
                             : make_float4(0.f, 0.f, 0.f, 0.f);
    }
}

// single fp16 round of A (2 cvt.rn.f16x2 + 1 store per float4)
__device__ __forceinline__ void store_A(const float4* rg, char* smem, int tid) {
    #pragma unroll
    for (int i = 0; i < 8; i++) {
        int idx = i * GT + tid;
        int m = idx >> 5, c4 = (idx & 31) << 2;
        __half2 p0 = __float22half2_rn(make_float2(rg[i].x, rg[i].y));
        __half2 p1 = __float22half2_rn(make_float2(rg[i].z, rg[i].w));
        int off = m * SK + c4 * 2;
        *reinterpret_cast<uint2*>(smem + S_AS + off) =
            make_uint2(*reinterpret_cast<uint32_t*>(&p0), *reinterpret_cast<uint32_t*>(&p1));
    }
}

// ================ GEMM: C[rows x 128] = A @ W + bias ================
// fp16 2-chain: A (rounded) x Whi + A x Wlo, fp32 accumulate.
__global__ void __launch_bounds__(GT, 1)
hmma_gemm_kernel(const float* __restrict__ A, const float* __restrict__ W,
                 const float* __restrict__ bias, float* __restrict__ C,
                 long rows, long ntiles) {
    extern __shared__ __align__(16) char smem[];
    const uint32_t sb = smem_u32(smem);
    const int tid = threadIdx.x, wid = tid >> 5, lane = tid & 31;
    const int mw = wid & 3, nw = wid >> 2;

    conv_W(W, smem, tid);

    const int q = lane >> 3, r = lane & 7;
    const uint32_t aRow = (uint32_t)(mw * 32 + r + (q & 1) * 8);
    const uint32_t a_kb = (uint32_t)((q >> 1) * 16);
    const uint32_t aS0 = sb + S_AS + aRow * SK + a_kb;
    const uint32_t aS1 = aS0 + 16 * SK;
    const uint32_t bRow = (uint32_t)(nw * 32 + r + (q >> 1) * 8);
    const uint32_t b_kb = (uint32_t)((q & 1) * 16);
    const uint32_t bHb = sb + S_WH + bRow * SK + b_kb;
    const uint32_t bLb = sb + S_WL + bRow * SK + b_kb;

    float4 rg[8];
    long t = blockIdx.x;
    stage_A(A, rows, t, rg, tid);
    __syncthreads();

    for (; t < ntiles; ) {
        store_A(rg, smem, tid);
        __syncthreads();

        long tn = t + gridDim.x;
        if (tn < ntiles) stage_A(A, rows, tn, rg, tid);

        float acc[32];
        #pragma unroll
        for (int i = 0; i < 32; i++) acc[i] = 0.f;

        #pragma unroll
        for (int ks = 0; ks < 8; ks++) {
            const uint32_t ko = ks * 32;
            uint32_t a00, a01, a02, a03, a10, a11, a12, a13;
            ldsm4(a00, a01, a02, a03, aS0 + ko);
            ldsm4(a10, a11, a12, a13, aS1 + ko);
            #pragma unroll
            for (int nb = 0; nb < 2; nb++) {
                const uint32_t off = (uint32_t)nb * (16 * SK) + ko;
                uint32_t xh0, xh1, xh2, xh3, xl0, xl1, xl2, xl3;
                ldsm4(xh0, xh1, xh2, xh3, bHb + off);
                ldsm4(xl0, xl1, xl2, xl3, bLb + off);
                float* c00 = acc + nb * 16;
                float* c01 = acc + nb * 16 + 4;
                float* c10 = acc + nb * 16 + 8;
                float* c11 = acc + nb * 16 + 12;
                // A x W_hi
                mma16816(c00, a00, a01, a02, a03, xh0, xh1);
                mma16816(c01, a00, a01, a02, a03, xh2, xh3);
                mma16816(c10, a10, a11, a12, a13, xh0, xh1);
                mma16816(c11, a10, a11, a12, a13, xh2, xh3);
                // A x W_lo
                mma16816(c00, a00, a01, a02, a03, xl0, xl1);
                mma16816(c01, a00, a01, a02, a03, xl2, xl3);
                mma16816(c10, a10, a11, a12, a13, xl0, xl1);
                mma16816(c11, a10, a11, a12, a13, xl2, xl3);
            }
        }

        const long mbase = t * 128 + mw * 32;
        #pragma unroll
        for (int nb = 0; nb < 2; nb++) {
            #pragma unroll
            for (int n8 = 0; n8 < 2; n8++) {
                int col = nw * 32 + nb * 16 + n8 * 8 + (lane & 3) * 2;
                float2 bb = *reinterpret_cast<const float2*>(bias + col);
                #pragma unroll
                for (int mb = 0; mb < 2; mb++) {
                    const float* cp = acc + nb * 16 + mb * 8 + n8 * 4;
                    long r0 = mbase + mb * 16 + (lane >> 2);
                    long r1 = r0 + 8;
                    if (r0 < rows)
                        *reinterpret_cast<float2*>(C + r0 * 128 + col) =
                            make_float2(cp[0] + bb.x, cp[1] + bb.y);
                    if (r1 < rows)
                        *reinterpret_cast<float2*>(C + r1 * 128 + col) =
                            make_float2(cp[2] + bb.x, cp[3] + bb.y);
                }
            }
        }
        __syncthreads();
        t = tn;
    }
}

// ================= non-GEMM kernels =================
__global__ void zero_kernel(int N) {
    long i = (long)blockIdx.x * blockDim.x + threadIdx.x;
    if (i < (long)N * 32) reinterpret_cast<float4*>(g_wV)[i] = make_float4(0.f, 0.f, 0.f, 0.f);
    if (i < (long)N * 2)  reinterpret_cast<float4*>(g_z)[i]  = make_float4(0.f, 0.f, 0.f, 0.f);
}

// 2 edges per warp: lanes 0-15 -> edge 0, lanes 16-31 -> edge 1; 8 floats per lane.
__global__ void __launch_bounds__(256)
edge_epilogue_kernel(const float* __restrict__ envelope,
                     const int* __restrict__ src, const int* __restrict__ dst,
                     float* __restrict__ eout, long E) {
    long gw = (long)blockIdx.x * 8 + (threadIdx.x >> 5);
    int lane = threadIdx.x & 31;
    long ed = gw * 2 + (lane >> 4);
    if (ed >= E) return;

    int si = __ldg(src + ed);
    int di = __ldg(dst + ed);
    float env = __ldg(envelope + ed);

    int c = (lane & 15) * 8;
    float kv[8], qv[8], vv[8], pv[8];
    ldg_el8(g_K + (long)si * 128 + c, kv);
    ldg_el8(g_Q + (long)di * 128 + c, qv);
    ldg_el8(g_V + (long)si * 128 + c, vv);
    float* ep = eout + ed * 128 + c;
    ldg_ef8(ep, pv);

    float sc[8];
    float part = 0.f;
    #pragma unroll
    for (int i = 0; i < 8; i++) {
        sc[i] = kv[i] * qv[i] * 0.25f * pv[i];
        part += sc[i];
    }
    part += __shfl_xor_sync(0xFFFFFFFFu, part, 1);
    float s = __expf(fminf(fmaxf(part, -5.f), 5.f));
    float es = env * s;

    stg_ef8(ep, sc);

    float* w = g_wV + (long)di * 128 + c;
    red_v4(w,     vv[0] * es, vv[1] * es, vv[2] * es, vv[3] * es);
    red_v4(w + 4, vv[4] * es, vv[5] * es, vv[6] * es, vv[7] * es);
    if ((lane & 1) == 0) red_f32(g_z + (long)di * 8 + ((lane & 15) >> 1), s);
}

__global__ void norm_kernel(float* __restrict__ vout, int N) {
    long i = (long)blockIdx.x * blockDim.x + threadIdx.x;
    if (i < (long)N * 32) {
        int n  = (int)(i >> 5);
        int c4 = (int)(i & 31);
        float4 w = reinterpret_cast<const float4*>(g_wV)[i];
        float zz = g_z[n * 8 + (c4 >> 2)] + 1e-6f;
        float inv = 1.0f / zz;
        reinterpret_cast<float4*>(vout)[i] =
            make_float4(w.x * inv, w.y * inv, w.z * inv, w.w * inv);
    }
}

extern "C" void kernel_launch(void* const* d_in, const int* in_sizes, int n_in,
                              void* d_out, int out_size) {
    const float* v        = (const float*)d_in[0];
    const float* e        = (const float*)d_in[1];
    const float* envelope = (const float*)d_in[2];
    const float* Wq       = (const float*)d_in[3];
    const float* bq       = (const float*)d_in[4];
    const float* Wk       = (const float*)d_in[5];
    const float* bk       = (const float*)d_in[6];
    const float* Wv       = (const float*)d_in[7];
    const float* bv       = (const float*)d_in[8];
    const float* We       = (const float*)d_in[9];
    const float* be       = (const float*)d_in[10];
    const int*   src      = (const int*)d_in[11];
    const int*   dst      = (const int*)d_in[12];

    int N = in_sizes[0] / 128;
    long E = in_sizes[11];

    float* out  = (float*)d_out;
    float* vout = out;
    float* eout = out + (long)N * 128;

    float *gq, *gk, *gv;
    cudaGetSymbolAddress((void**)&gq, g_Q);
    cudaGetSymbolAddress((void**)&gk, g_K);
    cudaGetSymbolAddress((void**)&gv, g_V);
    cudaFuncSetAttribute(hmma_gemm_kernel, cudaFuncAttributeMaxDynamicSharedMemorySize, S_TOT);

    long tilesN = (N + 127) / 128;
    long tilesE = (E + 127) / 128;
    int gridN = (int)((tilesN < 148) ? tilesN : 148);
    int gridE = (int)((tilesE < 148) ? tilesE : 148);

    zero_kernel<<<(int)(((long)N * 32 + 255) / 256), 256>>>(N);
    hmma_gemm_kernel<<<gridN, GT, S_TOT>>>(v, Wq, bq, gq, N, tilesN);
    hmma_gemm_kernel<<<gridN, GT, S_TOT>>>(v, Wk, bk, gk, N, tilesN);
    hmma_gemm_kernel<<<gridN, GT, S_TOT>>>(v, Wv, bv, gv, N, tilesN);
    hmma_gemm_kernel<<<gridE, GT, S_TOT>>>(e, We, be, eout, E, tilesE);
    edge_epilogue_kernel<<<(int)((E + 15) / 16), 256>>>(envelope, src, dst, eout, E);
    norm_kernel<<<(int)(((long)N * 32 + 255) / 256), 256>>>(vout, N);
}

// round 17
// speedup vs baseline: 1.7459x; 1.0050x over previous
#include <cuda_runtime.h>
#include <cuda_fp16.h>
#include <cstdint>

static const int MAXN = 50000;

__device__ float g_Q [MAXN * 128];
__device__ float g_K [MAXN * 128];
__device__ float g_V [MAXN * 128];
__device__ float g_wV[MAXN * 128];
__device__ float g_z [MAXN * 8];

// ================= helpers =================
__device__ __forceinline__ uint32_t smem_u32(const void* p) {
    uint32_t a;
    asm("{ .reg .u64 t; cvta.to.shared.u64 t, %1; cvt.u32.u64 %0, t; }" : "=r"(a) : "l"(p));
    return a;
}
__device__ __forceinline__ void ldsm4(uint32_t& r0, uint32_t& r1, uint32_t& r2, uint32_t& r3,
                                      uint32_t addr) {
    asm volatile("ldmatrix.sync.aligned.m8n8.x4.shared.b16 {%0,%1,%2,%3}, [%4];"
                 : "=r"(r0), "=r"(r1), "=r"(r2), "=r"(r3) : "r"(addr));
}
__device__ __forceinline__ void mma16816(float* c,
                                         uint32_t a0, uint32_t a1, uint32_t a2, uint32_t a3,
                                         uint32_t b0, uint32_t b1) {
    asm volatile("mma.sync.aligned.m16n8k16.row.col.f32.f16.f16.f32 "
                 "{%0,%1,%2,%3}, {%4,%5,%6,%7}, {%8,%9}, {%0,%1,%2,%3};"
                 : "+f"(c[0]), "+f"(c[1]), "+f"(c[2]), "+f"(c[3])
                 : "r"(a0), "r"(a1), "r"(a2), "r"(a3), "r"(b0), "r"(b1));
}
__device__ __forceinline__ void red_v4(float* p, float a, float b, float c, float d) {
    asm volatile("red.global.add.v4.f32 [%0], {%1, %2, %3, %4};"
                 :: "l"(p), "f"(a), "f"(b), "f"(c), "f"(d) : "memory");
}
__device__ __forceinline__ void red_f32(float* p, float a) {
    asm volatile("red.global.add.f32 [%0], %1;" :: "l"(p), "f"(a) : "memory");
}
__device__ __forceinline__ void ldg_el8(const float* p, float v[8]) {
    uint32_t r0,r1,r2,r3,r4,r5,r6,r7;
    asm volatile("ld.global.nc.L2::evict_last.v8.b32 {%0,%1,%2,%3,%4,%5,%6,%7}, [%8];"
                 : "=r"(r0),"=r"(r1),"=r"(r2),"=r"(r3),"=r"(r4),"=r"(r5),"=r"(r6),"=r"(r7)
                 : "l"(p));
    v[0]=__uint_as_float(r0); v[1]=__uint_as_float(r1);
    v[2]=__uint_as_float(r2); v[3]=__uint_as_float(r3);
    v[4]=__uint_as_float(r4); v[5]=__uint_as_float(r5);
    v[6]=__uint_as_float(r6); v[7]=__uint_as_float(r7);
}
__device__ __forceinline__ void ldg_ef8(const float* p, float v[8]) {
    uint32_t r0,r1,r2,r3,r4,r5,r6,r7;
    asm volatile("ld.global.L2::evict_first.v8.b32 {%0,%1,%2,%3,%4,%5,%6,%7}, [%8];"
                 : "=r"(r0),"=r"(r1),"=r"(r2),"=r"(r3),"=r"(r4),"=r"(r5),"=r"(r6),"=r"(r7)
                 : "l"(p));
    v[0]=__uint_as_float(r0); v[1]=__uint_as_float(r1);
    v[2]=__uint_as_float(r2); v[3]=__uint_as_float(r3);
    v[4]=__uint_as_float(r4); v[5]=__uint_as_float(r5);
    v[6]=__uint_as_float(r6); v[7]=__uint_as_float(r7);
}
__device__ __forceinline__ void stg_ef8(float* p, const float v[8]) {
    asm volatile("st.global.L2::evict_first.v8.b32 [%0], {%1,%2,%3,%4,%5,%6,%7,%8};"
                 :: "l"(p),
                    "r"(__float_as_uint(v[0])), "r"(__float_as_uint(v[1])),
                    "r"(__float_as_uint(v[2])), "r"(__float_as_uint(v[3])),
                    "r"(__float_as_uint(v[4])), "r"(__float_as_uint(v[5])),
                    "r"(__float_as_uint(v[6])), "r"(__float_as_uint(v[7]))
                 : "memory");
}

// ---- smem layout: padded 272B rows (16B pad -> ldmatrix conflict-free) ----
// A: single fp16 (34816B). W: fp16 hi + fp16 lo (34816B each). Total 102KB.
#define SK    272
#define S_AS  0
#define S_WH  34816
#define S_WL  69632
#define S_TOT 104448

#define GT 256   // 8 warps/CTA; warp grid 2M x 4N, warp tile M64 x N32

__device__ __forceinline__ void conv_W(const float* __restrict__ W, char* smem, int tid) {
    for (int i = tid; i < 4096; i += GT) {
        int k = i >> 5, n4 = (i & 31) << 2;
        float4 w = *reinterpret_cast<const float4*>(W + k * 128 + n4);
        const float* wp = &w.x;
        #pragma unroll
        for (int j = 0; j < 4; j++) {
            __half h = __float2half_rn(wp[j]);
            __half l = __float2half_rn(wp[j] - __half2float(h));
            int off = (n4 + j) * SK + k * 2;
            *reinterpret_cast<__half*>(smem + S_WH + off) = h;
            *reinterpret_cast<__half*>(smem + S_WL + off) = l;
        }
    }
}

// A tile: 128x128 fp32 = 4096 float4, 256 threads -> 16 per thread
__device__ __forceinline__ void stage_A(const float* __restrict__ A, long rows, long t,
                                        float4* rg, int tid) {
    #pragma unroll
    for (int i = 0; i < 16; i++) {
        int idx = i * GT + tid;
        int m = idx >> 5, c4 = (idx & 31) << 2;
        long row = t * 128 + m;
        rg[i] = (row < rows) ? *reinterpret_cast<const float4*>(A + row * 128 + c4)
                             : make_float4(0.f, 0.f, 0.f, 0.f);
    }
}

__device__ __forceinline__ void store_A(const float4* rg, char* smem, int tid) {
    #pragma unroll
    for (int i = 0; i < 16; i++) {
        int idx = i * GT + tid;
        int m = idx >> 5, c4 = (idx & 31) << 2;
        __half2 p0 = __float22half2_rn(make_float2(rg[i].x, rg[i].y));
        __half2 p1 = __float22half2_rn(make_float2(rg[i].z, rg[i].w));
        int off = m * SK + c4 * 2;
        *reinterpret_cast<uint2*>(smem + S_AS + off) =
            make_uint2(*reinterpret_cast<uint32_t*>(&p0), *reinterpret_cast<uint32_t*>(&p1));
    }
}

// ================ GEMM: C[rows x 128] = A @ W + bias ================
// fp16 2-chain, warp tile M64 x N32.
// acc layout: [mb*16 + nb*8 + n8*4 + i], mb = m16 block 0..3, nb = n16 block 0..1.
__global__ void __launch_bounds__(GT, 1)
hmma_gemm_kernel(const float* __restrict__ A, const float* __restrict__ W,
                 const float* __restrict__ bias, float* __restrict__ C,
                 long rows, long ntiles) {
    extern __shared__ __align__(16) char smem[];
    const uint32_t sb = smem_u32(smem);
    const int tid = threadIdx.x, wid = tid >> 5, lane = tid & 31;
    const int mw = wid & 1, nw = wid >> 1;

    conv_W(W, smem, tid);

    const int q = lane >> 3, r = lane & 7;
    // A fragment bases: four m16 blocks of this warp's M64 slice
    const uint32_t aRow = (uint32_t)(mw * 64 + r + (q & 1) * 8);
    const uint32_t a_kb = (uint32_t)((q >> 1) * 16);
    const uint32_t aS0 = sb + S_AS + aRow * SK + a_kb;
    const uint32_t aS1 = aS0 + 16 * SK;
    const uint32_t aS2 = aS0 + 32 * SK;
    const uint32_t aS3 = aS0 + 48 * SK;
    // B fragment base: this warp's N32 slice
    const uint32_t bRow = (uint32_t)(nw * 32 + r + (q >> 1) * 8);
    const uint32_t b_kb = (uint32_t)((q & 1) * 16);
    const uint32_t bHb = sb + S_WH + bRow * SK + b_kb;
    const uint32_t bLb = sb + S_WL + bRow * SK + b_kb;

    float4 rg[16];
    long t = blockIdx.x;
    stage_A(A, rows, t, rg, tid);
    __syncthreads();

    for (; t < ntiles; ) {
        store_A(rg, smem, tid);
        __syncthreads();

        long tn = t + gridDim.x;
        if (tn < ntiles) stage_A(A, rows, tn, rg, tid);

        float acc[64];
        #pragma unroll
        for (int i = 0; i < 64; i++) acc[i] = 0.f;

        #pragma unroll
        for (int ks = 0; ks < 8; ks++) {
            const uint32_t ko = ks * 32;
            uint32_t a0[4], a1[4], a2[4], a3[4];
            ldsm4(a0[0], a0[1], a0[2], a0[3], aS0 + ko);
            ldsm4(a1[0], a1[1], a1[2], a1[3], aS1 + ko);
            ldsm4(a2[0], a2[1], a2[2], a2[3], aS2 + ko);
            ldsm4(a3[0], a3[1], a3[2], a3[3], aS3 + ko);
            #pragma unroll
            for (int nb = 0; nb < 2; nb++) {
                const uint32_t off = (uint32_t)nb * (16 * SK) + ko;
                uint32_t xh0, xh1, xh2, xh3, xl0, xl1, xl2, xl3;
                ldsm4(xh0, xh1, xh2, xh3, bHb + off);
                ldsm4(xl0, xl1, xl2, xl3, bLb + off);
                float* c0 = acc + 0 * 16 + nb * 8;
                float* c1 = acc + 1 * 16 + nb * 8;
                float* c2 = acc + 2 * 16 + nb * 8;
                float* c3 = acc + 3 * 16 + nb * 8;
                // A x W_hi   (n8=0 -> +0, n8=1 -> +4)
                mma16816(c0,     a0[0], a0[1], a0[2], a0[3], xh0, xh1);
                mma16816(c0 + 4, a0[0], a0[1], a0[2], a0[3], xh2, xh3);
                mma16816(c1,     a1[0], a1[1], a1[2], a1[3], xh0, xh1);
                mma16816(c1 + 4, a1[0], a1[1], a1[2], a1[3], xh2, xh3);
                mma16816(c2,     a2[0], a2[1], a2[2], a2[3], xh0, xh1);
                mma16816(c2 + 4, a2[0], a2[1], a2[2], a2[3], xh2, xh3);
                mma16816(c3,     a3[0], a3[1], a3[2], a3[3], xh0, xh1);
                mma16816(c3 + 4, a3[0], a3[1], a3[2], a3[3], xh2, xh3);
                // A x W_lo
                mma16816(c0,     a0[0], a0[1], a0[2], a0[3], xl0, xl1);
                mma16816(c0 + 4, a0[0], a0[1], a0[2], a0[3], xl2, xl3);
                mma16816(c1,     a1[0], a1[1], a1[2], a1[3], xl0, xl1);
                mma16816(c1 + 4, a1[0], a1[1], a1[2], a1[3], xl2, xl3);
                mma16816(c2,     a2[0], a2[1], a2[2], a2[3], xl0, xl1);
                mma16816(c2 + 4, a2[0], a2[1], a2[2], a2[3], xl2, xl3);
                mma16816(c3,     a3[0], a3[1], a3[2], a3[3], xl0, xl1);
                mma16816(c3 + 4, a3[0], a3[1], a3[2], a3[3], xl2, xl3);
            }
        }

        // epilogue: add bias, store C.  acc[mb*16 + nb*8 + n8*4 + i]
        const long mbase = t * 128 + mw * 64;
        #pragma unroll
        for (int mb = 0; mb < 4; mb++) {
            #pragma unroll
            for (int nb = 0; nb < 2; nb++) {
                #pragma unroll
                for (int n8 = 0; n8 < 2; n8++) {
                    int col = nw * 32 + nb * 16 + n8 * 8 + (lane & 3) * 2;
                    float2 bb = *reinterpret_cast<const float2*>(bias + col);
                    const float* cp = acc + mb * 16 + nb * 8 + n8 * 4;
                    long r0 = mbase + mb * 16 + (lane >> 2);
                    long r1 = r0 + 8;
                    if (r0 < rows)
                        *reinterpret_cast<float2*>(C + r0 * 128 + col) =
                            make_float2(cp[0] + bb.x, cp[1] + bb.y);
                    if (r1 < rows)
                        *reinterpret_cast<float2*>(C + r1 * 128 + col) =
                            make_float2(cp[2] + bb.x, cp[3] + bb.y);
                }
            }
        }
        __syncthreads();
        t = tn;
    }
}

// ================= non-GEMM kernels =================
__global__ void zero_kernel(int N) {
    long i = (long)blockIdx.x * blockDim.x + threadIdx.x;
    if (i < (long)N * 32) reinterpret_cast<float4*>(g_wV)[i] = make_float4(0.f, 0.f, 0.f, 0.f);
    if (i < (long)N * 2)  reinterpret_cast<float4*>(g_z)[i]  = make_float4(0.f, 0.f, 0.f, 0.f);
}

// 2 edges per warp: lanes 0-15 -> edge 0, lanes 16-31 -> edge 1; 8 floats per lane.
__global__ void __launch_bounds__(256)
edge_epilogue_kernel(const float* __restrict__ envelope,
                     const int* __restrict__ src, const int* __restrict__ dst,
                     float* __restrict__ eout, long E) {
    long gw = (long)blockIdx.x * 8 + (threadIdx.x >> 5);
    int lane = threadIdx.x & 31;
    long ed = gw * 2 + (lane >> 4);
    if (ed >= E) return;

    int si = __ldg(src + ed);
    int di = __ldg(dst + ed);
    float env = __ldg(envelope + ed);

    int c = (lane & 15) * 8;
    float kv[8], qv[8], vv[8], pv[8];
    ldg_el8(g_K + (long)si * 128 + c, kv);
    ldg_el8(g_Q + (long)di * 128 + c, qv);
    ldg_el8(g_V + (long)si * 128 + c, vv);
    float* ep = eout + ed * 128 + c;
    ldg_ef8(ep, pv);

    float sc[8];
    float part = 0.f;
    #pragma unroll
    for (int i = 0; i < 8; i++) {
        sc[i] = kv[i] * qv[i] * 0.25f * pv[i];
        part += sc[i];
    }
    part += __shfl_xor_sync(0xFFFFFFFFu, part, 1);
    float s = __expf(fminf(fmaxf(part, -5.f), 5.f));
    float es = env * s;

    stg_ef8(ep, sc);

    float* w = g_wV + (long)di * 128 + c;
    red_v4(w,     vv[0] * es, vv[1] * es, vv[2] * es, vv[3] * es);
    red_v4(w + 4, vv[4] * es, vv[5] * es, vv[6] * es, vv[7] * es);
    if ((lane & 1) == 0) red_f32(g_z + (long)di * 8 + ((lane & 15) >> 1), s);
}

__global__ void norm_kernel(float* __restrict__ vout, int N) {
    long i = (long)blockIdx.x * blockDim.x + threadIdx.x;
    if (i < (long)N * 32) {
        int n  = (int)(i >> 5);
        int c4 = (int)(i & 31);
        float4 w = reinterpret_cast<const float4*>(g_wV)[i];
        float zz = g_z[n * 8 + (c4 >> 2)] + 1e-6f;
        float inv = 1.0f / zz;
        reinterpret_cast<float4*>(vout)[i] =
            make_float4(w.x * inv, w.y * inv, w.z * inv, w.w * inv);
    }
}

extern "C" void kernel_launch(void* const* d_in, const int* in_sizes, int n_in,
                              void* d_out, int out_size) {
    const float* v        = (const float*)d_in[0];
    const float* e        = (const float*)d_in[1];
    const float* envelope = (const float*)d_in[2];
    const float* Wq       = (const float*)d_in[3];
    const float* bq       = (const float*)d_in[4];
    const float* Wk       = (const float*)d_in[5];
    const float* bk       = (const float*)d_in[6];
    const float* Wv       = (const float*)d_in[7];
    const float* bv       = (const float*)d_in[8];
    const float* We       = (const float*)d_in[9];
    const float* be       = (const float*)d_in[10];
    const int*   src      = (const int*)d_in[11];
    const int*   dst      = (const int*)d_in[12];

    int N = in_sizes[0] / 128;
    long E = in_sizes[11];

    float* out  = (float*)d_out;
    float* vout = out;
    float* eout = out + (long)N * 128;

    float *gq, *gk, *gv;
    cudaGetSymbolAddress((void**)&gq, g_Q);
    cudaGetSymbolAddress((void**)&gk, g_K);
    cudaGetSymbolAddress((void**)&gv, g_V);
    cudaFuncSetAttribute(hmma_gemm_kernel, cudaFuncAttributeMaxDynamicSharedMemorySize, S_TOT);

    long tilesN = (N + 127) / 128;
    long tilesE = (E + 127) / 128;
    int gridN = (int)((tilesN < 148) ? tilesN : 148);
    int gridE = (int)((tilesE < 148) ? tilesE : 148);

    zero_kernel<<<(int)(((long)N * 32 + 255) / 256), 256>>>(N);
    hmma_gemm_kernel<<<gridN, GT, S_TOT>>>(v, Wq, bq, gq, N, tilesN);
    hmma_gemm_kernel<<<gridN, GT, S_TOT>>>(v, Wk, bk, gk, N, tilesN);
    hmma_gemm_kernel<<<gridN, GT, S_TOT>>>(v, Wv, bv, gv, N, tilesN);
    hmma_gemm_kernel<<<gridE, GT, S_TOT>>>(e, We, be, eout, E, tilesE);
    edge_epilogue_kernel<<<(int)((E + 15) / 16), 256>>>(envelope, src, dst, eout, E);
    norm_kernel<<<(int)(((long)N * 32 + 255) / 256), 256>>>(vout, N);
}